// round 14
// baseline (speedup 1.0000x reference)
#include <cuda_runtime.h>
#include <math.h>
#include <stdint.h>

// Problem constants
#define BB 8
#define TT 1025
#define CC 512
#define NH 8
#define CH 256   // CACHE
#define LL 256

// ---------------- scratch (device globals; no allocation allowed) ----------
__device__ float g_qkv[(size_t)BB*TT*3*CC];   // fused q|k|v, row stride 1536
__device__ float g_ao[(size_t)BB*TT*CC];
__device__ float g_xself[(size_t)BB*TT*CC];
__device__ float g_cat[(size_t)BB*LL*2*CH];
__device__ float g_cat2[(size_t)BB*LL*2*CH];
__device__ float g_rz[(size_t)BB*LL*2*CH];    // fused r|z
__device__ float g_add[(size_t)BB*LL*CH];
__device__ float g_grn[(size_t)BB*LL*CH];
__device__ float g_q2[(size_t)BB*TT*CH];
__device__ float g_kv2[(size_t)BB*LL*2*CH];   // fused k2|v2
__device__ float g_ao2[(size_t)BB*TT*CH];
__device__ float g_xmem[(size_t)BB*TT*CH];

// ---------------- helpers ----------------------------------------------------
__device__ __forceinline__ float to_tf32(float x) {
    uint32_t u;
    asm("cvt.rna.tf32.f32 %0, %1;" : "=r"(u) : "f"(x));
    return __uint_as_float(u);
}

__device__ __forceinline__ uint32_t smem_u32(const void* p) {
    uint32_t a;
    asm("{ .reg .u64 t; cvta.to.shared.u64 t, %1; cvt.u32.u64 %0, t; }" : "=r"(a) : "l"(p));
    return a;
}

__device__ __forceinline__ void cp16(uint32_t dst, const void* src) {
    asm volatile("cp.async.cg.shared.global [%0], [%1], 16;" :: "r"(dst), "l"(src));
}
#define CP_COMMIT() asm volatile("cp.async.commit_group;" ::: "memory")
#define CP_WAIT0()  asm volatile("cp.async.wait_group 0;" ::: "memory")

// bulk async copy global->shared with mbarrier transaction completion
__device__ __forceinline__ void cpbulk(uint32_t dst, const void* src,
                                       uint32_t bytes, uint32_t mbar) {
    asm volatile(
        "cp.async.bulk.shared::cluster.global.mbarrier::complete_tx::bytes "
        "[%0], [%1], %2, [%3];"
        :: "r"(dst), "l"(src), "r"(bytes), "r"(mbar) : "memory");
}
#define MB_INIT(mb) \
    asm volatile("mbarrier.init.shared.b64 [%0], 1;" :: "r"(mb) : "memory")
#define MB_EXPECT(mb, bytes) \
    asm volatile("mbarrier.arrive.expect_tx.shared.b64 _, [%0], %1;" \
                 :: "r"(mb), "r"((uint32_t)(bytes)) : "memory")

__device__ __forceinline__ void mbar_wait(uint32_t mbar, uint32_t parity) {
    asm volatile(
        "{\n\t.reg .pred P;\n\t"
        "WL_%=:\n\t"
        "mbarrier.try_wait.parity.acquire.cta.shared::cta.b64 P, [%0], %1;\n\t"
        "@!P bra WL_%=;\n\t}"
        :: "r"(mbar), "r"(parity) : "memory");
}

__device__ __forceinline__ void mma8(float* d, const float* a, const float* b) {
    asm volatile(
        "mma.sync.aligned.m16n8k8.row.col.f32.tf32.tf32.f32 "
        "{%0,%1,%2,%3}, {%4,%5,%6,%7}, {%8,%9}, {%0,%1,%2,%3};"
        : "+f"(d[0]), "+f"(d[1]), "+f"(d[2]), "+f"(d[3])
        : "r"(__float_as_uint(a[0])), "r"(__float_as_uint(a[1])),
          "r"(__float_as_uint(a[2])), "r"(__float_as_uint(a[3])),
          "r"(__float_as_uint(b[0])), "r"(__float_as_uint(b[1])));
}

__device__ __forceinline__ float actf(float v, int act) {
    if (act == 1) return 1.f / (1.f + expf(-v));                       // sigmoid
    if (act == 2) return 0.5f * v * (1.f + erff(v * 0.70710678118654752f)); // exact gelu
    return v;
}

__device__ __forceinline__ float redmax4(float v) {
    v = fmaxf(v, __shfl_xor_sync(0xffffffffu, v, 1));
    v = fmaxf(v, __shfl_xor_sync(0xffffffffu, v, 2));
    return v;
}
__device__ __forceinline__ float redsum4(float v) {
    v += __shfl_xor_sync(0xffffffffu, v, 1);
    v += __shfl_xor_sync(0xffffffffu, v, 2);
    return v;
}

// ---------------- bulk-copy 3-stage tf32 GEMM, segmented B --------------------
// C[:, n] = act( scale * A @ Bseg[n/segsz][:, n%segsz] + biasseg[...] )
// BK=32: A rows 128B, B rows 512B -> one cp.async.bulk per row (160 issues
// per k-group vs 2048 LDGSTS). 3-stage mbarrier pipeline, 2 blocks/SM.
#define BK2 32
#define A_LD 36
#define B_LD 136
#define A_SZ (128 * A_LD)     // 4608 floats / stage
#define B_SZ (BK2 * B_LD)     // 4352 floats / stage

__global__ void __launch_bounds__(256)
gemm_cp(int M, int N, int K,
        const float* __restrict__ A, int lda,
        const float* __restrict__ B0, const float* __restrict__ B1,
        const float* __restrict__ B2, int segsz, int ldb,
        float* __restrict__ C, int ldc,
        const float* __restrict__ b0, const float* __restrict__ b1,
        const float* __restrict__ b2,
        float scale, int act)
{
    constexpr int NT = 4;
    extern __shared__ float sm[];
    uint32_t smb = smem_u32(sm);
    const uint32_t mb0 = smb;                 // 3 mbarriers at +0, +8, +16
    float* As = sm + 8;                       // 32B offset, 16B aligned
    float* Bs = sm + 8 + 3 * A_SZ;
    uint32_t asb = smem_u32(As), bsb = smem_u32(Bs);

    int tid = threadIdx.x, lane = tid & 31, wid = tid >> 5;
    int wm = wid >> 2, wn = wid & 3;          // 2 x 4 warps, warp tile 64x32
    int g = lane >> 2, t = lane & 3;
    int m0 = blockIdx.y * 128, n0 = blockIdx.x * 128;

    // segment select (uniform per block)
    int seg = n0 / segsz;
    const float* B    = (seg == 0) ? B0 : (seg == 1) ? B1 : B2;
    const float* bias = (seg == 0) ? b0 : (seg == 1) ? b1 : b2;
    int nb = n0 - seg * segsz;

    float acc[4][NT][4];
    #pragma unroll
    for (int i = 0; i < 4; i++)
        #pragma unroll
        for (int j = 0; j < NT; j++)
            #pragma unroll
            for (int q = 0; q < 4; q++) acc[i][j][q] = 0.f;

    int NK = K / BK2;
    const uint32_t GRPB = 128 * BK2 * 4 + BK2 * 512;   // 32768 bytes / group

    auto issue = [&](int kt, int s) {
        int k0 = kt * BK2;
        if (tid < 128) {                          // A: one 128B row per thread
            int gm = m0 + tid; if (gm >= M) gm = M - 1;
            cpbulk(asb + (uint32_t)(s * A_SZ + tid * A_LD) * 4,
                   A + (size_t)gm * lda + k0, BK2 * 4, mb0 + 8u * s);
        } else if (tid < 128 + BK2) {             // B: one 512B row per thread
            int r = tid - 128;
            cpbulk(bsb + (uint32_t)(s * B_SZ + r * B_LD) * 4,
                   B + (size_t)(k0 + r) * ldb + nb, 512, mb0 + 8u * s);
        }
    };

    if (tid == 0) {
        MB_INIT(mb0); MB_INIT(mb0 + 8); MB_INIT(mb0 + 16);
        MB_EXPECT(mb0, GRPB);
        MB_EXPECT(mb0 + 8, GRPB);
        MB_EXPECT(mb0 + 16, GRPB);
    }
    __syncthreads();              // init+expect visible before any issue
    issue(0, 0);
    if (NK > 1) issue(1, 1);

    uint32_t ph0 = 0, ph1 = 0, ph2 = 0;
    for (int kt = 0; kt < NK; kt++) {
        int s = kt - (kt / 3) * 3;
        uint32_t mb = mb0 + 8u * s;
        if (s == 0)      { mbar_wait(mb, ph0); ph0 ^= 1; }
        else if (s == 1) { mbar_wait(mb, ph1); ph1 ^= 1; }
        else             { mbar_wait(mb, ph2); ph2 ^= 1; }
        // post expect for the next group that reuses this barrier (kt+3);
        // ordered before its issues by the end-of-iteration __syncthreads.
        if (tid == 0 && kt + 3 < NK) MB_EXPECT(mb, GRPB);

        const float* as = As + s * A_SZ;
        const float* bs = Bs + s * B_SZ;
        #pragma unroll
        for (int kk = 0; kk < BK2; kk += 8) {
            float af[4][4], bf[NT][2];
            #pragma unroll
            for (int mt = 0; mt < 4; mt++) {
                int mr = wm * 64 + mt * 16 + g;
                af[mt][0] = as[mr * A_LD + kk + t];
                af[mt][1] = as[(mr + 8) * A_LD + kk + t];
                af[mt][2] = as[mr * A_LD + kk + t + 4];
                af[mt][3] = as[(mr + 8) * A_LD + kk + t + 4];
            }
            #pragma unroll
            for (int nt = 0; nt < NT; nt++) {
                int nc = wn * 32 + nt * 8 + g;
                bf[nt][0] = bs[(kk + t) * B_LD + nc];
                bf[nt][1] = bs[(kk + t + 4) * B_LD + nc];
            }
            #pragma unroll
            for (int mt = 0; mt < 4; mt++)
                #pragma unroll
                for (int nt = 0; nt < NT; nt++)
                    mma8(acc[mt][nt], af[mt], bf[nt]);
        }
        __syncthreads();          // stage (kt+2)%3 fully consumed by all
        if (kt + 2 < NK) issue(kt + 2, (kt + 2) % 3);
    }

    // epilogue
    #pragma unroll
    for (int mt = 0; mt < 4; mt++) {
        int mr = m0 + wm * 64 + mt * 16 + g;
        #pragma unroll
        for (int nt = 0; nt < NT; nt++) {
            int ncl = wn * 32 + nt * 8 + 2 * t;
            int nc = n0 + ncl;
            if (nc < N) {
                float bv0 = bias[nb + ncl];
                float bv1 = bias[nb + ncl + 1];
                if (mr < M) {
                    float2 v;
                    v.x = actf(acc[mt][nt][0] * scale + bv0, act);
                    v.y = actf(acc[mt][nt][1] * scale + bv1, act);
                    *(float2*)&C[(size_t)mr * ldc + nc] = v;
                }
                if (mr + 8 < M) {
                    float2 v;
                    v.x = actf(acc[mt][nt][2] * scale + bv0, act);
                    v.y = actf(acc[mt][nt][3] * scale + bv1, act);
                    *(float2*)&C[(size_t)(mr + 8) * ldc + nc] = v;
                }
            }
        }
    }
}

// ---------------- flash attention (BKV=64, bulk K/V, RNA in place) ------------
// O = softmax(scale * Q Kt) V per (b, h). BQ=128, BKV=64, row-major tiles.
// K/V rows loaded with one cp.async.bulk each (128 issues vs 2048 LDGSTS).
template<int DH>
__global__ void __launch_bounds__(256, 2)
flash_k(const float* __restrict__ Q, long long qbat, int ldq,
        const float* __restrict__ K, long long kbat, int ldk,
        const float* __restrict__ V, int ldv,
        float* __restrict__ O, long long obat, int ldo,
        int Tq, int Tkv, float scale)
{
    constexpr int BQ = 128, BKV = 64;
    constexpr int LD = DH + 4, LP = BKV + 4;
    constexpr int CQ = DH / 4;
    constexpr int NTS = BKV / 8;
    constexpr uint32_t KVB = 2u * BKV * DH * 4;   // bytes per KV tile
    extern __shared__ float sm[];
    uint32_t smb = smem_u32(sm);
    const uint32_t mb = smb;                   // 1 mbarrier at +0
    float* Qs = sm + 4;                        // 16B offset
    float* Ks = Qs + BQ * LD;
    float* Vs = Ks + BKV * LD;
    float* Ps = Vs + BKV * LD;
    uint32_t qsb = smem_u32(Qs), ksb = smem_u32(Ks), vsb = smem_u32(Vs);

    int tid = threadIdx.x, lane = tid & 31, wid = tid >> 5;
    int g = lane >> 2, t = lane & 3;
    int bh = blockIdx.y, b = bh / NH, h = bh % NH;
    const float* qp = Q + (long long)b * qbat + h * DH;
    const float* kp = K + (long long)b * kbat + h * DH;
    const float* vp = V + (long long)b * kbat + h * DH;
    float*       op = O + (long long)b * obat + h * DH;
    int q0 = blockIdx.x * BQ;
    int mr = wid * 16 + g;

    // Q tile via cp16 (once)
    #pragma unroll
    for (int i = 0; i < BQ * CQ / 256; i++) {
        int idx = tid + i * 256;
        int m = idx / CQ, q = idx % CQ;
        int gm = q0 + m; if (gm >= Tq) gm = Tq - 1;
        cp16(qsb + (uint32_t)(m * LD + q * 4) * 4, qp + (size_t)gm * ldq + q * 4);
    }
    CP_COMMIT();

    if (tid == 0) { MB_INIT(mb); MB_EXPECT(mb, KVB); }
    uint32_t ph = 0;

    float m0 = -1e30f, m1 = -1e30f, l0 = 0.f, l1 = 0.f;
    float oacc[DH / 8][4];
    #pragma unroll
    for (int i = 0; i < DH / 8; i++)
        #pragma unroll
        for (int j = 0; j < 4; j++) oacc[i][j] = 0.f;

    int ntk = (Tkv + BKV - 1) / BKV;
    for (int kt = 0; kt < ntk; kt++) {
        int kvb = kt * BKV;
        __syncthreads();       // prev tile consumed; init/expect visible
        if (tid < BKV) {
            int gn = kvb + tid; if (gn >= Tkv) gn = Tkv - 1;
            cpbulk(ksb + (uint32_t)(tid * LD) * 4, kp + (size_t)gn * ldk, DH * 4, mb);
        } else if (tid < 2 * BKV) {
            int n = tid - BKV;
            int gn = kvb + n; if (gn >= Tkv) gn = Tkv - 1;
            cpbulk(vsb + (uint32_t)(n * LD) * 4, vp + (size_t)gn * ldv, DH * 4, mb);
        }
        mbar_wait(mb, ph); ph ^= 1;
        if (tid == 0 && kt + 1 < ntk) MB_EXPECT(mb, KVB);

        // in-place RNA tf32 conversion (any thread; data visible post-wait)
        if (kt == 0) {
            CP_WAIT0();        // Q copies complete
            #pragma unroll
            for (int i = 0; i < BQ * CQ / 256; i++) {
                int idx = tid + i * 256;
                int m = idx / CQ, q = idx % CQ;
                float4* p = (float4*)&Qs[m * LD + q * 4];
                float4 v = *p;
                v.x = to_tf32(v.x); v.y = to_tf32(v.y);
                v.z = to_tf32(v.z); v.w = to_tf32(v.w);
                *p = v;
            }
        }
        #pragma unroll
        for (int i = 0; i < BKV * CQ / 256; i++) {
            int idx = tid + i * 256;
            int n = idx / CQ, q = idx % CQ;
            float4* pk = (float4*)&Ks[n * LD + q * 4];
            float4 vk = *pk;
            vk.x = to_tf32(vk.x); vk.y = to_tf32(vk.y);
            vk.z = to_tf32(vk.z); vk.w = to_tf32(vk.w);
            *pk = vk;
            float4* pv = (float4*)&Vs[n * LD + q * 4];
            float4 vv = *pv;
            vv.x = to_tf32(vv.x); vv.y = to_tf32(vv.y);
            vv.z = to_tf32(vv.z); vv.w = to_tf32(vv.w);
            *pv = vv;
        }
        __syncthreads();

        // S = Q Kt
        float sacc[NTS][4];
        #pragma unroll
        for (int nt = 0; nt < NTS; nt++)
            #pragma unroll
            for (int j = 0; j < 4; j++) sacc[nt][j] = 0.f;
        #pragma unroll
        for (int kk = 0; kk < DH; kk += 8) {
            float af[4];
            af[0] = Qs[mr * LD + kk + t];
            af[1] = Qs[(mr + 8) * LD + kk + t];
            af[2] = Qs[mr * LD + kk + t + 4];
            af[3] = Qs[(mr + 8) * LD + kk + t + 4];
            #pragma unroll
            for (int nt = 0; nt < NTS; nt++) {
                int nc = nt * 8 + g;
                float bf[2] = { Ks[nc * LD + kk + t], Ks[nc * LD + kk + t + 4] };
                mma8(sacc[nt], af, bf);
            }
        }

        // scale + mask + row max
        float mt0 = -1e30f, mt1 = -1e30f;
        #pragma unroll
        for (int nt = 0; nt < NTS; nt++) {
            #pragma unroll
            for (int j = 0; j < 2; j++) {
                int col = kvb + nt * 8 + 2 * t + j;
                float s0 = (col < Tkv) ? sacc[nt][j] * scale : -1e30f;
                float s1 = (col < Tkv) ? sacc[nt][2 + j] * scale : -1e30f;
                sacc[nt][j] = s0; sacc[nt][2 + j] = s1;
                mt0 = fmaxf(mt0, s0); mt1 = fmaxf(mt1, s1);
            }
        }
        mt0 = redmax4(mt0); mt1 = redmax4(mt1);
        float mn0 = fmaxf(m0, mt0), mn1 = fmaxf(m1, mt1);
        float a0 = __expf(m0 - mn0), a1 = __expf(m1 - mn1);

        float sum0 = 0.f, sum1 = 0.f;
        #pragma unroll
        for (int nt = 0; nt < NTS; nt++) {
            #pragma unroll
            for (int j = 0; j < 2; j++) {
                float p0 = __expf(sacc[nt][j] - mn0);
                float p1 = __expf(sacc[nt][2 + j] - mn1);
                sum0 += p0; sum1 += p1;
                Ps[mr * LP + nt * 8 + 2 * t + j] = to_tf32(p0);
                Ps[(mr + 8) * LP + nt * 8 + 2 * t + j] = to_tf32(p1);
            }
        }
        sum0 = redsum4(sum0); sum1 = redsum4(sum1);
        l0 = l0 * a0 + sum0; l1 = l1 * a1 + sum1;
        m0 = mn0; m1 = mn1;
        #pragma unroll
        for (int n2 = 0; n2 < DH / 8; n2++) {
            oacc[n2][0] *= a0; oacc[n2][1] *= a0;
            oacc[n2][2] *= a1; oacc[n2][3] *= a1;
        }
        __syncwarp();

        // O += P V
        #pragma unroll
        for (int kk = 0; kk < BKV; kk += 8) {
            float af[4];
            af[0] = Ps[mr * LP + kk + t];
            af[1] = Ps[(mr + 8) * LP + kk + t];
            af[2] = Ps[mr * LP + kk + t + 4];
            af[3] = Ps[(mr + 8) * LP + kk + t + 4];
            #pragma unroll
            for (int n2 = 0; n2 < DH / 8; n2++) {
                int nc = n2 * 8 + g;
                float bf[2] = { Vs[(kk + t) * LD + nc], Vs[(kk + t + 4) * LD + nc] };
                mma8(oacc[n2], af, bf);
            }
        }
    }

    float inv0 = 1.f / l0, inv1 = 1.f / l1;
    int r0 = q0 + mr, r1 = r0 + 8;
    #pragma unroll
    for (int n2 = 0; n2 < DH / 8; n2++) {
        int nc = n2 * 8 + 2 * t;
        if (r0 < Tq) {
            float2 v; v.x = oacc[n2][0] * inv0; v.y = oacc[n2][1] * inv0;
            *(float2*)&op[(size_t)r0 * ldo + nc] = v;
        }
        if (r1 < Tq) {
            float2 v; v.x = oacc[n2][2] * inv1; v.y = oacc[n2][3] * inv1;
            *(float2*)&op[(size_t)r1 * ldo + nc] = v;
        }
    }
}

// ---------------- block reductions -----------------------------------------
__device__ __forceinline__ float blkSum(float v) {
    __shared__ float sh[32];
    int lane = threadIdx.x & 31, w = threadIdx.x >> 5;
    #pragma unroll
    for (int o = 16; o > 0; o >>= 1) v += __shfl_xor_sync(0xffffffffu, v, o);
    if (lane == 0) sh[w] = v;
    __syncthreads();
    int nw = (blockDim.x + 31) >> 5;
    v = (threadIdx.x < nw) ? sh[threadIdx.x] : 0.f;
    if (w == 0) {
        #pragma unroll
        for (int o = 16; o > 0; o >>= 1) v += __shfl_xor_sync(0xffffffffu, v, o);
        if (lane == 0) sh[0] = v;
    }
    __syncthreads();
    float r = sh[0];
    __syncthreads();
    return r;
}

// ---------------- grouped conv -> pos (2 channels/thread, shared taps) -------
__global__ void conv_pos_k(const float* __restrict__ x,
                           const float* __restrict__ w,
                           const float* __restrict__ b,
                           float* __restrict__ out)
{
    int bt = blockIdx.x;
    int bb = bt / TT, t = bt % TT;
    int c0 = threadIdx.x * 2;
    long long obase = (long long)bt * CC + c0;
    if (t == 0) {
        *(float2*)&out[obase] = make_float2(0.f, 0.f);
        return;
    }
    int p = t - 1, hh = p >> 5, ww = p & 31;
    const float* wc0 = w + (long long)c0 * 18;
    const float* wc1 = wc0 + 18;
    float acc0 = b[c0], acc1 = b[c0 + 1];
    #pragma unroll
    for (int kh = 0; kh < 3; kh++) {
        int y = hh + kh - 1;
        if (y < 0 || y >= 32) continue;
        #pragma unroll
        for (int kw = 0; kw < 3; kw++) {
            int xw = ww + kw - 1;
            if (xw < 0 || xw >= 32) continue;
            long long xb = ((long long)bb * TT + 1 + y * 32 + xw) * CC;
            float2 xv = *(const float2*)(x + xb + c0);
            acc0 = fmaf(wc0[kh * 3 + kw],     xv.x, acc0);
            acc0 = fmaf(wc0[9 + kh * 3 + kw], xv.y, acc0);
            acc1 = fmaf(wc1[kh * 3 + kw],     xv.x, acc1);
            acc1 = fmaf(wc1[9 + kh * 3 + kw], xv.y, acc1);
        }
    }
    *(float2*)&out[obase] = make_float2(acc0, acc1);
}

// ---------------- concat [gr, x_summary] ------------------------------------
__global__ void cat_k(const float* __restrict__ grc,
                      const float* __restrict__ xself,
                      float* __restrict__ cat)
{
    int row = blockIdx.x;
    int b = row / LL, l = row % LL;
    int c = threadIdx.x;
    float v;
    if (c < CH) v = grc[l * CH + c];
    else {
        int t = (l * TT) / LL;
        v = xself[((long long)b * TT + t) * CC + (c - CH)];
    }
    cat[(long long)row * 2 * CH + c] = v;
}

// ---------------- concat [reset*gr, x_summary] -------------------------------
__global__ void cat2_k(const float* __restrict__ rz,
                       const float* __restrict__ grc,
                       const float* __restrict__ cat,
                       float* __restrict__ cat2)
{
    int row = blockIdx.x;
    int l = row % LL;
    int c = threadIdx.x;
    float v;
    if (c < CH) v = rz[(long long)row * 2 * CH + c] * grc[l * CH + c];
    else        v = cat[(long long)row * 2 * CH + c];
    cat2[(long long)row * 2 * CH + c] = v;
}

// ---------------- layernorm + GRU blend --------------------------------------
__global__ void gru_ln_k(const float* __restrict__ add,
                         const float* __restrict__ rz,
                         const float* __restrict__ grc,
                         const float* __restrict__ gamma,
                         const float* __restrict__ beta,
                         float* __restrict__ grn)
{
    int row = blockIdx.x;
    int l = row % LL;
    int c = threadIdx.x;
    float a = add[(long long)row * CH + c];
    float mu = blkSum(a) * (1.f / CH);
    float d = a - mu;
    float var = blkSum(d * d) * (1.f / CH);
    float nv = d * rsqrtf(var + 1e-5f) * gamma[c] + beta[c];
    float zz = rz[(long long)row * 2 * CH + CH + c];
    grn[(long long)row * CH + c] = zz * nv + (1.f - zz) * grc[l * CH + c];
}

// ---------------- final blend: out = pos + alpha*mem_pad + (1-a)*xself -------
__global__ void blend_k(const float* __restrict__ xself,
                        const float* __restrict__ xmem,
                        const float* __restrict__ lam,
                        float* __restrict__ out)
{
    long long n = (long long)BB * TT * CC;
    for (long long i = (long long)blockIdx.x * blockDim.x + threadIdx.x;
         i < n; i += (long long)gridDim.x * blockDim.x) {
        int c = (int)(i % CC);
        long long bt = i / CC;
        int h = c >> 6, d = c & 63;
        float alpha = 1.f / (1.f + expf(-lam[h]));
        float mem = (d < 32) ? xmem[bt * CH + h * 32 + d] : 0.f;
        out[i] += alpha * mem + (1.f - alpha) * xself[i];
    }
}

// ---------------- host helpers -----------------------------------------------
static float* gptr(const void* sym_) {
    void* p = nullptr;
    cudaGetSymbolAddress(&p, sym_);
    return (float*)p;
}

#define GSM ((8 + 3 * A_SZ + 3 * B_SZ) * 4)   // 107552 B

static void mmseg(int M, int N, int K, const float* A, int lda,
                  const float* B0, const float* B1, const float* B2,
                  int segsz, int ldb, float* C, int ldc,
                  const float* b0, const float* b1, const float* b2,
                  float scale, int act)
{
    dim3 g(N / 128, (M + 127) / 128);
    gemm_cp<<<g, 256, GSM>>>(M, N, K, A, lda, B0, B1, B2, segsz, ldb,
                             C, ldc, b0, b1, b2, scale, act);
}

extern "C" void kernel_launch(void* const* d_in, const int* in_sizes, int n_in,
                              void* d_out, int out_size)
{
    const float* x    = (const float*)d_in[0];
    const float* grc  = (const float*)d_in[1];
    const float* Wq1  = (const float*)d_in[2];  const float* bq1 = (const float*)d_in[3];
    const float* Wk1  = (const float*)d_in[4];  const float* bk1 = (const float*)d_in[5];
    const float* Wv1  = (const float*)d_in[6];  const float* bv1 = (const float*)d_in[7];
    const float* Wo1  = (const float*)d_in[8];  const float* bo1 = (const float*)d_in[9];
    const float* Wq2  = (const float*)d_in[10]; const float* bq2 = (const float*)d_in[11];
    const float* Wk2  = (const float*)d_in[12]; const float* bk2 = (const float*)d_in[13];
    const float* Wv2  = (const float*)d_in[14]; const float* bv2 = (const float*)d_in[15];
    const float* Wo2  = (const float*)d_in[16]; const float* bo2 = (const float*)d_in[17];
    const float* Wr   = (const float*)d_in[18]; const float* br  = (const float*)d_in[19];
    const float* Wz   = (const float*)d_in[20]; const float* bz  = (const float*)d_in[21];
    const float* Wa   = (const float*)d_in[22]; const float* ba  = (const float*)d_in[23];
    const float* gamma= (const float*)d_in[24]; const float* beta= (const float*)d_in[25];
    const float* lam  = (const float*)d_in[26];
    const float* convw= (const float*)d_in[27]; const float* convb=(const float*)d_in[28];
    float* out = (float*)d_out;

    float* qkv = gptr(g_qkv); float* ao = gptr(g_ao);  float* xs = gptr(g_xself);
    float* cat= gptr(g_cat);  float* cat2=gptr(g_cat2);
    float* rz = gptr(g_rz);   float* ad = gptr(g_add); float* grn= gptr(g_grn);
    float* q2 = gptr(g_q2);   float* kv2= gptr(g_kv2);
    float* ao2= gptr(g_ao2);  float* xm = gptr(g_xmem);

    const int M1 = BB * TT;      // 8200
    const int MG = BB * LL;      // 2048

    const int SM64 = (4 + 128*68 + 64*68 + 64*68 + 128*68) * 4;   // 104464
    const int SM32 = (4 + 128*36 + 64*36 + 64*36 + 128*68) * 4;   // 71696
    static int cfg = 0;
    if (!cfg) {
        cudaFuncSetAttribute(flash_k<64>, cudaFuncAttributeMaxDynamicSharedMemorySize, SM64);
        cudaFuncSetAttribute(flash_k<32>, cudaFuncAttributeMaxDynamicSharedMemorySize, SM32);
        cudaFuncSetAttribute(gemm_cp, cudaFuncAttributeMaxDynamicSharedMemorySize, GSM);
        cfg = 1;
    }

    // 1) positional conv -> out (2 channels/thread)
    conv_pos_k<<<BB * TT, 256>>>(x, convw, convb, out);

    // 2) fused QKV projection: [M1][1536], segmented B = Wq1|Wk1|Wv1
    mmseg(M1, 3 * CC, CC, x, CC, Wq1, Wk1, Wv1, CC, CC,
          qkv, 3 * CC, bq1, bk1, bv1, 1.f, 0);

    // 3) flash attention 1 (dh=64)
    {
        dim3 g((TT + 127) / 128, BB * NH);
        flash_k<64><<<g, 256, SM64>>>(
            qkv,          (long long)TT * 3 * CC, 3 * CC,
            qkv + CC,     (long long)TT * 3 * CC, 3 * CC,
            qkv + 2 * CC, 3 * CC,
            ao,           (long long)TT * CC, CC,
            TT, TT, 0.125f);
    }

    // 4) x_self = O @ Wo1 + bo1
    mmseg(M1, CC, CC, ao, CC, Wo1, Wo1, Wo1, CC, CC,
          xs, CC, bo1, bo1, bo1, 1.f, 0);

    // 5) GRU cache update (r|z via segmented B = Wr|Wz)
    cat_k<<<MG, 2 * CH>>>(grc, xs, cat);
    mmseg(MG, 2 * CH, 2 * CH, cat, 2 * CH, Wr, Wz, Wz, CH, CH,
          rz, 2 * CH, br, bz, bz, 1.f, 1);
    cat2_k<<<MG, 2 * CH>>>(rz, grc, cat, cat2);
    mmseg(MG, CH, 2 * CH, cat2, 2 * CH, Wa, Wa, Wa, CH, CH,
          ad, CH, ba, ba, ba, 1.f, 2);
    gru_ln_k<<<MG, CH>>>(ad, rz, grc, gamma, beta, grn);

    // 6) MHA2 projections (q2 standalone; k2|v2 via segmented B)
    mmseg(M1, CH, CH, x, CC, Wq2, Wq2, Wq2, CH, CH,
          q2, CH, bq2, bq2, bq2, 1.f, 0);
    mmseg(MG, 2 * CH, CH, grn, CH, Wk2, Wv2, Wv2, CH, CH,
          kv2, 2 * CH, bk2, bv2, bv2, 1.f, 0);

    // 7) flash attention 2 (dh=32, kv=256)
    {
        dim3 g((TT + 127) / 128, BB * NH);
        flash_k<32><<<g, 256, SM32>>>(
            q2,       (long long)TT * CH, CH,
            kv2,      (long long)LL * 2 * CH, 2 * CH,
            kv2 + CH, 2 * CH,
            ao2,      (long long)TT * CH, CH,
            TT, LL, 0.1767766952966369f);
    }

    // 8) x_mem = O2 @ Wo2 + bo2
    mmseg(M1, CH, CH, ao2, CH, Wo2, Wo2, Wo2, CH, CH,
          xm, CH, bo2, bo2, bo2, 1.f, 0);

    // 9) final blend into out
    blend_k<<<4096, 256>>>(xs, xm, lam, out);
}

// round 16
// speedup vs baseline: 1.1022x; 1.1022x over previous
#include <cuda_runtime.h>
#include <math.h>
#include <stdint.h>

// Problem constants
#define BB 8
#define TT 1025
#define CC 512
#define NH 8
#define CH 256   // CACHE
#define LL 256

// ---------------- scratch (device globals; no allocation allowed) ----------
__device__ float g_qkv[(size_t)BB*TT*3*CC];   // fused q|k|v, row stride 1536
__device__ float g_ao[(size_t)BB*TT*CC];
__device__ float g_xself[(size_t)BB*TT*CC];
__device__ float g_cat[(size_t)BB*LL*2*CH];
__device__ float g_cat2[(size_t)BB*LL*2*CH];
__device__ float g_rz[(size_t)BB*LL*2*CH];    // fused r|z
__device__ float g_add[(size_t)BB*LL*CH];
__device__ float g_grn[(size_t)BB*LL*CH];
__device__ float g_q2[(size_t)BB*TT*CH];
__device__ float g_kv2[(size_t)BB*LL*2*CH];   // fused k2|v2
__device__ float g_ao2[(size_t)BB*TT*CH];
__device__ float g_xmem[(size_t)BB*TT*CH];

// ---------------- helpers ----------------------------------------------------
__device__ __forceinline__ float to_tf32(float x) {
    uint32_t u;
    asm("cvt.rna.tf32.f32 %0, %1;" : "=r"(u) : "f"(x));
    return __uint_as_float(u);
}

__device__ __forceinline__ uint32_t smem_u32(const void* p) {
    uint32_t a;
    asm("{ .reg .u64 t; cvta.to.shared.u64 t, %1; cvt.u32.u64 %0, t; }" : "=r"(a) : "l"(p));
    return a;
}

__device__ __forceinline__ void cp16(uint32_t dst, const void* src) {
    asm volatile("cp.async.cg.shared.global [%0], [%1], 16;" :: "r"(dst), "l"(src));
}
#define CP_COMMIT() asm volatile("cp.async.commit_group;" ::: "memory")
#define CP_WAIT1()  asm volatile("cp.async.wait_group 1;" ::: "memory")

__device__ __forceinline__ void mma8(float* d, const float* a, const float* b) {
    asm volatile(
        "mma.sync.aligned.m16n8k8.row.col.f32.tf32.tf32.f32 "
        "{%0,%1,%2,%3}, {%4,%5,%6,%7}, {%8,%9}, {%0,%1,%2,%3};"
        : "+f"(d[0]), "+f"(d[1]), "+f"(d[2]), "+f"(d[3])
        : "r"(__float_as_uint(a[0])), "r"(__float_as_uint(a[1])),
          "r"(__float_as_uint(a[2])), "r"(__float_as_uint(a[3])),
          "r"(__float_as_uint(b[0])), "r"(__float_as_uint(b[1])));
}

__device__ __forceinline__ float actf(float v, int act) {
    if (act == 1) return 1.f / (1.f + expf(-v));                       // sigmoid
    if (act == 2) return 0.5f * v * (1.f + erff(v * 0.70710678118654752f)); // exact gelu
    return v;
}

__device__ __forceinline__ float redmax4(float v) {
    v = fmaxf(v, __shfl_xor_sync(0xffffffffu, v, 1));
    v = fmaxf(v, __shfl_xor_sync(0xffffffffu, v, 2));
    return v;
}
__device__ __forceinline__ float redsum4(float v) {
    v += __shfl_xor_sync(0xffffffffu, v, 1);
    v += __shfl_xor_sync(0xffffffffu, v, 2);
    return v;
}

// ---------------- cp.async 3-stage tf32 GEMM, segmented B ---------------------
// C[:, n] = act( scale * A @ Bseg[n/segsz][:, n%segsz] + biasseg[...] )
// RACE FIX: the tail iterations commit EMPTY groups so that CP_WAIT1 at
// iteration kt always retires group kt (previously the last k-group could be
// read before its copies completed -> run-to-run nondeterminism).
#define G_LDA 20
#define G_LDB 136
#define G_ASZ (128 * G_LDA)
#define G_BSZ (16 * G_LDB)

__global__ void __launch_bounds__(256)
gemm_cp(int M, int N, int K,
        const float* __restrict__ A, int lda,
        const float* __restrict__ B0, const float* __restrict__ B1,
        const float* __restrict__ B2, int segsz, int ldb,
        float* __restrict__ C, int ldc,
        const float* __restrict__ b0, const float* __restrict__ b1,
        const float* __restrict__ b2,
        float scale, int act)
{
    constexpr int BM = 128, BN = 128, BK = 16, NT = 4;
    extern __shared__ float sm[];
    float* As = sm;
    float* Bs = sm + 3 * G_ASZ;
    uint32_t asb = smem_u32(As), bsb = smem_u32(Bs);

    int tid = threadIdx.x, lane = tid & 31, wid = tid >> 5;
    int wm = wid >> 2, wn = wid & 3;
    int g = lane >> 2, t = lane & 3;
    int m0 = blockIdx.y * BM, n0 = blockIdx.x * BN;

    int seg = n0 / segsz;
    const float* B    = (seg == 0) ? B0 : (seg == 1) ? B1 : B2;
    const float* bias = (seg == 0) ? b0 : (seg == 1) ? b1 : b2;
    int nb = n0 - seg * segsz;

    float acc[4][NT][4];
    #pragma unroll
    for (int i = 0; i < 4; i++)
        #pragma unroll
        for (int j = 0; j < NT; j++)
            #pragma unroll
            for (int q = 0; q < 4; q++) acc[i][j][q] = 0.f;

    auto issue = [&](int kt, int s) {
        int k0 = kt * BK;
        #pragma unroll
        for (int i = 0; i < 2; i++) {
            int idx = tid + i * 256;
            int m = idx >> 2, q = idx & 3;
            int gm = m0 + m; if (gm >= M) gm = M - 1;
            cp16(asb + (uint32_t)(s * G_ASZ + m * G_LDA + q * 4) * 4,
                 A + (size_t)gm * lda + k0 + q * 4);
        }
        #pragma unroll
        for (int i = 0; i < 2; i++) {
            int idx = tid + i * 256;
            int k = idx >> 5, n4 = idx & 31;
            cp16(bsb + (uint32_t)(s * G_BSZ + k * G_LDB + n4 * 4) * 4,
                 B + (size_t)(k0 + k) * ldb + nb + n4 * 4);
        }
        CP_COMMIT();
    };

    int NK = K / BK;
    issue(0, 0);
    issue(1, 1);

    for (int kt = 0; kt < NK; kt++) {
        int s = kt - (kt / 3) * 3;
        CP_WAIT1();
        __syncthreads();
        const float* as = As + s * G_ASZ;
        const float* bs = Bs + s * G_BSZ;
        #pragma unroll
        for (int kk = 0; kk < BK; kk += 8) {
            float af[4][4], bf[NT][2];
            #pragma unroll
            for (int mt = 0; mt < 4; mt++) {
                int mr = wm * 64 + mt * 16 + g;
                af[mt][0] = as[mr * G_LDA + kk + t];
                af[mt][1] = as[(mr + 8) * G_LDA + kk + t];
                af[mt][2] = as[mr * G_LDA + kk + t + 4];
                af[mt][3] = as[(mr + 8) * G_LDA + kk + t + 4];
            }
            #pragma unroll
            for (int nt = 0; nt < NT; nt++) {
                int nc = wn * 32 + nt * 8 + g;
                bf[nt][0] = bs[(kk + t) * G_LDB + nc];
                bf[nt][1] = bs[(kk + t + 4) * G_LDB + nc];
            }
            #pragma unroll
            for (int mt = 0; mt < 4; mt++)
                #pragma unroll
                for (int nt = 0; nt < NT; nt++)
                    mma8(acc[mt][nt], af[mt], bf[nt]);
        }
        __syncthreads();
        if (kt + 2 < NK) issue(kt + 2, (kt + 2) - ((kt + 2) / 3) * 3);
        else             CP_COMMIT();          // RACE FIX: empty group keeps
                                               // WAIT1 retiring group kt+1
    }

    #pragma unroll
    for (int mt = 0; mt < 4; mt++) {
        int mr = m0 + wm * 64 + mt * 16 + g;
        #pragma unroll
        for (int nt = 0; nt < NT; nt++) {
            int ncl = wn * 32 + nt * 8 + 2 * t;
            int nc = n0 + ncl;
            if (nc < N) {
                float bv0 = bias[nb + ncl];
                float bv1 = bias[nb + ncl + 1];
                if (mr < M) {
                    float2 v;
                    v.x = actf(acc[mt][nt][0] * scale + bv0, act);
                    v.y = actf(acc[mt][nt][1] * scale + bv1, act);
                    *(float2*)&C[(size_t)mr * ldc + nc] = v;
                }
                if (mr + 8 < M) {
                    float2 v;
                    v.x = actf(acc[mt][nt][2] * scale + bv0, act);
                    v.y = actf(acc[mt][nt][3] * scale + bv1, act);
                    *(float2*)&C[(size_t)(mr + 8) * ldc + nc] = v;
                }
            }
        }
    }
}

// ---------------- flash attention (BKV=64, sync LDG+cvt staging) --------------
// O = softmax(scale * Q Kt) V per (b, h). BQ=128, BKV=64, row-major tiles.
// No cp.async anywhere -> no async races. 2 blocks/SM.
template<int DH>
__global__ void __launch_bounds__(256, 2)
flash_k(const float* __restrict__ Q, long long qbat, int ldq,
        const float* __restrict__ K, long long kbat, int ldk,
        const float* __restrict__ V, int ldv,
        float* __restrict__ O, long long obat, int ldo,
        int Tq, int Tkv, float scale)
{
    constexpr int BQ = 128, BKV = 64;
    constexpr int LD = DH + 4, LP = BKV + 4;
    constexpr int CQ = DH / 4;
    constexpr int NTS = BKV / 8;
    extern __shared__ float sm[];
    float* Qs = sm;                            // [BQ][LD]
    float* Ks = Qs + BQ * LD;                  // [BKV][LD]
    float* Vs = Ks + BKV * LD;                 // [BKV][LD]
    float* Ps = Vs + BKV * LD;                 // [BQ][LP]

    int tid = threadIdx.x, lane = tid & 31, wid = tid >> 5;
    int g = lane >> 2, t = lane & 3;
    int bh = blockIdx.y, b = bh / NH, h = bh % NH;
    const float* qp = Q + (long long)b * qbat + h * DH;
    const float* kp = K + (long long)b * kbat + h * DH;
    const float* vp = V + (long long)b * kbat + h * DH;
    float*       op = O + (long long)b * obat + h * DH;
    int q0 = blockIdx.x * BQ;
    int mr = wid * 16 + g;

    // Q tile: LDG.128 -> cvt.rna -> STS.128 (once)
    #pragma unroll
    for (int i = 0; i < BQ * CQ / 256; i++) {
        int idx = tid + i * 256;
        int m = idx / CQ, q = idx % CQ;
        int gm = q0 + m; if (gm >= Tq) gm = Tq - 1;
        float4 v = *(const float4*)(qp + (size_t)gm * ldq + q * 4);
        v.x = to_tf32(v.x); v.y = to_tf32(v.y);
        v.z = to_tf32(v.z); v.w = to_tf32(v.w);
        *(float4*)&Qs[m * LD + q * 4] = v;
    }

    float m0 = -1e30f, m1 = -1e30f, l0 = 0.f, l1 = 0.f;
    float oacc[DH / 8][4];
    #pragma unroll
    for (int i = 0; i < DH / 8; i++)
        #pragma unroll
        for (int j = 0; j < 4; j++) oacc[i][j] = 0.f;

    int ntk = (Tkv + BKV - 1) / BKV;
    for (int kt = 0; kt < ntk; kt++) {
        int kvb = kt * BKV;
        __syncthreads();                       // previous tile fully consumed
        #pragma unroll
        for (int i = 0; i < BKV * CQ / 256; i++) {
            int idx = tid + i * 256;
            int n = idx / CQ, q = idx % CQ;
            int gn = kvb + n; if (gn >= Tkv) gn = Tkv - 1;
            float4 vk = *(const float4*)(kp + (size_t)gn * ldk + q * 4);
            vk.x = to_tf32(vk.x); vk.y = to_tf32(vk.y);
            vk.z = to_tf32(vk.z); vk.w = to_tf32(vk.w);
            *(float4*)&Ks[n * LD + q * 4] = vk;
            float4 vv = *(const float4*)(vp + (size_t)gn * ldv + q * 4);
            vv.x = to_tf32(vv.x); vv.y = to_tf32(vv.y);
            vv.z = to_tf32(vv.z); vv.w = to_tf32(vv.w);
            *(float4*)&Vs[n * LD + q * 4] = vv;
        }
        __syncthreads();

        // S = Q Kt
        float sacc[NTS][4];
        #pragma unroll
        for (int nt = 0; nt < NTS; nt++)
            #pragma unroll
            for (int j = 0; j < 4; j++) sacc[nt][j] = 0.f;
        #pragma unroll
        for (int kk = 0; kk < DH; kk += 8) {
            float af[4];
            af[0] = Qs[mr * LD + kk + t];
            af[1] = Qs[(mr + 8) * LD + kk + t];
            af[2] = Qs[mr * LD + kk + t + 4];
            af[3] = Qs[(mr + 8) * LD + kk + t + 4];
            #pragma unroll
            for (int nt = 0; nt < NTS; nt++) {
                int nc = nt * 8 + g;
                float bf[2] = { Ks[nc * LD + kk + t], Ks[nc * LD + kk + t + 4] };
                mma8(sacc[nt], af, bf);
            }
        }

        // scale + mask + row max
        float mt0 = -1e30f, mt1 = -1e30f;
        #pragma unroll
        for (int nt = 0; nt < NTS; nt++) {
            #pragma unroll
            for (int j = 0; j < 2; j++) {
                int col = kvb + nt * 8 + 2 * t + j;
                float s0 = (col < Tkv) ? sacc[nt][j] * scale : -1e30f;
                float s1 = (col < Tkv) ? sacc[nt][2 + j] * scale : -1e30f;
                sacc[nt][j] = s0; sacc[nt][2 + j] = s1;
                mt0 = fmaxf(mt0, s0); mt1 = fmaxf(mt1, s1);
            }
        }
        mt0 = redmax4(mt0); mt1 = redmax4(mt1);
        float mn0 = fmaxf(m0, mt0), mn1 = fmaxf(m1, mt1);
        float a0 = __expf(m0 - mn0), a1 = __expf(m1 - mn1);

        float sum0 = 0.f, sum1 = 0.f;
        #pragma unroll
        for (int nt = 0; nt < NTS; nt++) {
            #pragma unroll
            for (int j = 0; j < 2; j++) {
                float p0 = __expf(sacc[nt][j] - mn0);
                float p1 = __expf(sacc[nt][2 + j] - mn1);
                sum0 += p0; sum1 += p1;
                Ps[mr * LP + nt * 8 + 2 * t + j] = to_tf32(p0);
                Ps[(mr + 8) * LP + nt * 8 + 2 * t + j] = to_tf32(p1);
            }
        }
        sum0 = redsum4(sum0); sum1 = redsum4(sum1);
        l0 = l0 * a0 + sum0; l1 = l1 * a1 + sum1;
        m0 = mn0; m1 = mn1;
        #pragma unroll
        for (int n2 = 0; n2 < DH / 8; n2++) {
            oacc[n2][0] *= a0; oacc[n2][1] *= a0;
            oacc[n2][2] *= a1; oacc[n2][3] *= a1;
        }
        __syncwarp();

        // O += P V
        #pragma unroll
        for (int kk = 0; kk < BKV; kk += 8) {
            float af[4];
            af[0] = Ps[mr * LP + kk + t];
            af[1] = Ps[(mr + 8) * LP + kk + t];
            af[2] = Ps[mr * LP + kk + t + 4];
            af[3] = Ps[(mr + 8) * LP + kk + t + 4];
            #pragma unroll
            for (int n2 = 0; n2 < DH / 8; n2++) {
                int nc = n2 * 8 + g;
                float bf[2] = { Vs[(kk + t) * LD + nc], Vs[(kk + t + 4) * LD + nc] };
                mma8(oacc[n2], af, bf);
            }
        }
    }

    float inv0 = 1.f / l0, inv1 = 1.f / l1;
    int r0 = q0 + mr, r1 = r0 + 8;
    #pragma unroll
    for (int n2 = 0; n2 < DH / 8; n2++) {
        int nc = n2 * 8 + 2 * t;
        if (r0 < Tq) {
            float2 v; v.x = oacc[n2][0] * inv0; v.y = oacc[n2][1] * inv0;
            *(float2*)&op[(size_t)r0 * ldo + nc] = v;
        }
        if (r1 < Tq) {
            float2 v; v.x = oacc[n2][2] * inv1; v.y = oacc[n2][3] * inv1;
            *(float2*)&op[(size_t)r1 * ldo + nc] = v;
        }
    }
}

// ---------------- block reductions -----------------------------------------
__device__ __forceinline__ float blkSum(float v) {
    __shared__ float sh[32];
    int lane = threadIdx.x & 31, w = threadIdx.x >> 5;
    #pragma unroll
    for (int o = 16; o > 0; o >>= 1) v += __shfl_xor_sync(0xffffffffu, v, o);
    if (lane == 0) sh[w] = v;
    __syncthreads();
    int nw = (blockDim.x + 31) >> 5;
    v = (threadIdx.x < nw) ? sh[threadIdx.x] : 0.f;
    if (w == 0) {
        #pragma unroll
        for (int o = 16; o > 0; o >>= 1) v += __shfl_xor_sync(0xffffffffu, v, o);
        if (lane == 0) sh[0] = v;
    }
    __syncthreads();
    float r = sh[0];
    __syncthreads();
    return r;
}

// ---------------- grouped conv -> pos (2 channels/thread, shared taps) -------
__global__ void conv_pos_k(const float* __restrict__ x,
                           const float* __restrict__ w,
                           const float* __restrict__ b,
                           float* __restrict__ out)
{
    int bt = blockIdx.x;
    int bb = bt / TT, t = bt % TT;
    int c0 = threadIdx.x * 2;
    long long obase = (long long)bt * CC + c0;
    if (t == 0) {
        *(float2*)&out[obase] = make_float2(0.f, 0.f);
        return;
    }
    int p = t - 1, hh = p >> 5, ww = p & 31;
    const float* wc0 = w + (long long)c0 * 18;
    const float* wc1 = wc0 + 18;
    float acc0 = b[c0], acc1 = b[c0 + 1];
    #pragma unroll
    for (int kh = 0; kh < 3; kh++) {
        int y = hh + kh - 1;
        if (y < 0 || y >= 32) continue;
        #pragma unroll
        for (int kw = 0; kw < 3; kw++) {
            int xw = ww + kw - 1;
            if (xw < 0 || xw >= 32) continue;
            long long xb = ((long long)bb * TT + 1 + y * 32 + xw) * CC;
            float2 xv = *(const float2*)(x + xb + c0);
            acc0 = fmaf(wc0[kh * 3 + kw],     xv.x, acc0);
            acc0 = fmaf(wc0[9 + kh * 3 + kw], xv.y, acc0);
            acc1 = fmaf(wc1[kh * 3 + kw],     xv.x, acc1);
            acc1 = fmaf(wc1[9 + kh * 3 + kw], xv.y, acc1);
        }
    }
    *(float2*)&out[obase] = make_float2(acc0, acc1);
}

// ---------------- concat [gr, x_summary] ------------------------------------
__global__ void cat_k(const float* __restrict__ grc,
                      const float* __restrict__ xself,
                      float* __restrict__ cat)
{
    int row = blockIdx.x;
    int b = row / LL, l = row % LL;
    int c = threadIdx.x;
    float v;
    if (c < CH) v = grc[l * CH + c];
    else {
        int t = (l * TT) / LL;
        v = xself[((long long)b * TT + t) * CC + (c - CH)];
    }
    cat[(long long)row * 2 * CH + c] = v;
}

// ---------------- concat [reset*gr, x_summary] -------------------------------
__global__ void cat2_k(const float* __restrict__ rz,
                       const float* __restrict__ grc,
                       const float* __restrict__ cat,
                       float* __restrict__ cat2)
{
    int row = blockIdx.x;
    int l = row % LL;
    int c = threadIdx.x;
    float v;
    if (c < CH) v = rz[(long long)row * 2 * CH + c] * grc[l * CH + c];
    else        v = cat[(long long)row * 2 * CH + c];
    cat2[(long long)row * 2 * CH + c] = v;
}

// ---------------- layernorm + GRU blend --------------------------------------
__global__ void gru_ln_k(const float* __restrict__ add,
                         const float* __restrict__ rz,
                         const float* __restrict__ grc,
                         const float* __restrict__ gamma,
                         const float* __restrict__ beta,
                         float* __restrict__ grn)
{
    int row = blockIdx.x;
    int l = row % LL;
    int c = threadIdx.x;
    float a = add[(long long)row * CH + c];
    float mu = blkSum(a) * (1.f / CH);
    float d = a - mu;
    float var = blkSum(d * d) * (1.f / CH);
    float nv = d * rsqrtf(var + 1e-5f) * gamma[c] + beta[c];
    float zz = rz[(long long)row * 2 * CH + CH + c];
    grn[(long long)row * CH + c] = zz * nv + (1.f - zz) * grc[l * CH + c];
}

// ---------------- final blend: out = pos + alpha*mem_pad + (1-a)*xself -------
__global__ void blend_k(const float* __restrict__ xself,
                        const float* __restrict__ xmem,
                        const float* __restrict__ lam,
                        float* __restrict__ out)
{
    long long n = (long long)BB * TT * CC;
    for (long long i = (long long)blockIdx.x * blockDim.x + threadIdx.x;
         i < n; i += (long long)gridDim.x * blockDim.x) {
        int c = (int)(i % CC);
        long long bt = i / CC;
        int h = c >> 6, d = c & 63;
        float alpha = 1.f / (1.f + expf(-lam[h]));
        float mem = (d < 32) ? xmem[bt * CH + h * 32 + d] : 0.f;
        out[i] += alpha * mem + (1.f - alpha) * xself[i];
    }
}

// ---------------- host helpers -----------------------------------------------
static float* gptr(const void* sym_) {
    void* p = nullptr;
    cudaGetSymbolAddress(&p, sym_);
    return (float*)p;
}

#define GSM ((3 * G_ASZ + 3 * G_BSZ) * 4)   // 56832 B

static void mmseg(int M, int N, int K, const float* A, int lda,
                  const float* B0, const float* B1, const float* B2,
                  int segsz, int ldb, float* C, int ldc,
                  const float* b0, const float* b1, const float* b2,
                  float scale, int act)
{
    dim3 g(N / 128, (M + 127) / 128);
    gemm_cp<<<g, 256, GSM>>>(M, N, K, A, lda, B0, B1, B2, segsz, ldb,
                             C, ldc, b0, b1, b2, scale, act);
}

extern "C" void kernel_launch(void* const* d_in, const int* in_sizes, int n_in,
                              void* d_out, int out_size)
{
    const float* x    = (const float*)d_in[0];
    const float* grc  = (const float*)d_in[1];
    const float* Wq1  = (const float*)d_in[2];  const float* bq1 = (const float*)d_in[3];
    const float* Wk1  = (const float*)d_in[4];  const float* bk1 = (const float*)d_in[5];
    const float* Wv1  = (const float*)d_in[6];  const float* bv1 = (const float*)d_in[7];
    const float* Wo1  = (const float*)d_in[8];  const float* bo1 = (const float*)d_in[9];
    const float* Wq2  = (const float*)d_in[10]; const float* bq2 = (const float*)d_in[11];
    const float* Wk2  = (const float*)d_in[12]; const float* bk2 = (const float*)d_in[13];
    const float* Wv2  = (const float*)d_in[14]; const float* bv2 = (const float*)d_in[15];
    const float* Wo2  = (const float*)d_in[16]; const float* bo2 = (const float*)d_in[17];
    const float* Wr   = (const float*)d_in[18]; const float* br  = (const float*)d_in[19];
    const float* Wz   = (const float*)d_in[20]; const float* bz  = (const float*)d_in[21];
    const float* Wa   = (const float*)d_in[22]; const float* ba  = (const float*)d_in[23];
    const float* gamma= (const float*)d_in[24]; const float* beta= (const float*)d_in[25];
    const float* lam  = (const float*)d_in[26];
    const float* convw= (const float*)d_in[27]; const float* convb=(const float*)d_in[28];
    float* out = (float*)d_out;

    float* qkv = gptr(g_qkv); float* ao = gptr(g_ao);  float* xs = gptr(g_xself);
    float* cat= gptr(g_cat);  float* cat2=gptr(g_cat2);
    float* rz = gptr(g_rz);   float* ad = gptr(g_add); float* grn= gptr(g_grn);
    float* q2 = gptr(g_q2);   float* kv2= gptr(g_kv2);
    float* ao2= gptr(g_ao2);  float* xm = gptr(g_xmem);

    const int M1 = BB * TT;      // 8200
    const int MG = BB * LL;      // 2048

    const int SM64 = (128*68 + 64*68 + 64*68 + 128*68) * 4;   // 104448
    const int SM32 = (128*36 + 64*36 + 64*36 + 128*68) * 4;   // 71680
    static int cfg = 0;
    if (!cfg) {
        cudaFuncSetAttribute(flash_k<64>, cudaFuncAttributeMaxDynamicSharedMemorySize, SM64);
        cudaFuncSetAttribute(flash_k<32>, cudaFuncAttributeMaxDynamicSharedMemorySize, SM32);
        cudaFuncSetAttribute(gemm_cp, cudaFuncAttributeMaxDynamicSharedMemorySize, GSM);
        cfg = 1;
    }

    // 1) positional conv -> out (2 channels/thread)
    conv_pos_k<<<BB * TT, 256>>>(x, convw, convb, out);

    // 2) fused QKV projection: [M1][1536], segmented B = Wq1|Wk1|Wv1
    mmseg(M1, 3 * CC, CC, x, CC, Wq1, Wk1, Wv1, CC, CC,
          qkv, 3 * CC, bq1, bk1, bv1, 1.f, 0);

    // 3) flash attention 1 (dh=64)
    {
        dim3 g((TT + 127) / 128, BB * NH);
        flash_k<64><<<g, 256, SM64>>>(
            qkv,          (long long)TT * 3 * CC, 3 * CC,
            qkv + CC,     (long long)TT * 3 * CC, 3 * CC,
            qkv + 2 * CC, 3 * CC,
            ao,           (long long)TT * CC, CC,
            TT, TT, 0.125f);
    }

    // 4) x_self = O @ Wo1 + bo1
    mmseg(M1, CC, CC, ao, CC, Wo1, Wo1, Wo1, CC, CC,
          xs, CC, bo1, bo1, bo1, 1.f, 0);

    // 5) GRU cache update (r|z via segmented B = Wr|Wz)
    cat_k<<<MG, 2 * CH>>>(grc, xs, cat);
    mmseg(MG, 2 * CH, 2 * CH, cat, 2 * CH, Wr, Wz, Wz, CH, CH,
          rz, 2 * CH, br, bz, bz, 1.f, 1);
    cat2_k<<<MG, 2 * CH>>>(rz, grc, cat, cat2);
    mmseg(MG, CH, 2 * CH, cat2, 2 * CH, Wa, Wa, Wa, CH, CH,
          ad, CH, ba, ba, ba, 1.f, 2);
    gru_ln_k<<<MG, CH>>>(ad, rz, grc, gamma, beta, grn);

    // 6) MHA2 projections (q2 standalone; k2|v2 via segmented B)
    mmseg(M1, CH, CH, x, CC, Wq2, Wq2, Wq2, CH, CH,
          q2, CH, bq2, bq2, bq2, 1.f, 0);
    mmseg(MG, 2 * CH, CH, grn, CH, Wk2, Wv2, Wv2, CH, CH,
          kv2, 2 * CH, bk2, bv2, bv2, 1.f, 0);

    // 7) flash attention 2 (dh=32, kv=256)
    {
        dim3 g((TT + 127) / 128, BB * NH);
        flash_k<32><<<g, 256, SM32>>>(
            q2,       (long long)TT * CH, CH,
            kv2,      (long long)LL * 2 * CH, 2 * CH,
            kv2 + CH, 2 * CH,
            ao2,      (long long)TT * CH, CH,
            TT, LL, 0.1767766952966369f);
    }

    // 8) x_mem = O2 @ Wo2 + bo2
    mmseg(M1, CH, CH, ao2, CH, Wo2, Wo2, Wo2, CH, CH,
          xm, CH, bo2, bo2, bo2, 1.f, 0);

    // 9) final blend into out
    blend_k<<<4096, 256>>>(xs, xm, lam, out);
}